// round 1
// baseline (speedup 1.0000x reference)
#include <cuda_runtime.h>
#include <cuda_bf16.h>

#define BB 32
#define LL 512
#define DD 256
#define FF 256
#define TL 16   // L positions per conv block

// Scratch (allocation-free rule): h1 = post-conv1/LN/ReLU activations
__device__ float g_h1[BB * LL * FF];
__device__ int   g_cs[BB * LL];

// ---------------------------------------------------------------------------
// Kernel 1: per-batch inclusive cumsum of durations (L=512)
// ---------------------------------------------------------------------------
__global__ void cumsum_kernel(const int* __restrict__ dur) {
    __shared__ int s[LL];
    int t = threadIdx.x;
    int b = blockIdx.x;
    s[t] = dur[b * LL + t];
    for (int off = 1; off < LL; off <<= 1) {
        __syncthreads();
        int v = (t >= off) ? s[t - off] : 0;
        __syncthreads();
        s[t] += v;
    }
    g_cs[b * LL + t] = s[t];
}

// ---------------------------------------------------------------------------
// Kernel 2: expand — one warp per output frame, binary search + float4 copy
// grid: (M/8, B), block 256
// ---------------------------------------------------------------------------
__global__ void expand_kernel(const float* __restrict__ x,
                              float* __restrict__ out, int M) {
    __shared__ int cs[LL];
    int b = blockIdx.y;
    for (int i = threadIdx.x; i < LL; i += blockDim.x)
        cs[i] = g_cs[b * LL + i];
    __syncthreads();

    int warp = threadIdx.x >> 5;
    int lane = threadIdx.x & 31;
    int frame = blockIdx.x * 8 + warp;
    if (frame >= M) return;

    int total = cs[LL - 1];
    // upper_bound: smallest i with cs[i] > frame
    int lo = 0, hi = LL;
    while (lo < hi) {
        int mid = (lo + hi) >> 1;
        if (cs[mid] > frame) hi = mid; else lo = mid + 1;
    }
    int idx = lo < (LL - 1) ? lo : (LL - 1);
    bool valid = frame < total;

    const float4* src = reinterpret_cast<const float4*>(x + ((size_t)b * LL + idx) * DD);
    float4* dst = reinterpret_cast<float4*>(out + ((size_t)b * M + frame) * DD);
    float4 z = make_float4(0.f, 0.f, 0.f, 0.f);
    dst[lane]      = valid ? src[lane]      : z;
    dst[lane + 32] = valid ? src[lane + 32] : z;
}

// ---------------------------------------------------------------------------
// Kernel 3/4: conv1d(K=3, same-pad) + LayerNorm + ReLU, optionally fused
// linear head (h @ lw + lb, ReLU) instead of storing activations.
// grid: (L/TL, B), block 256 (thread = output channel f)
// ---------------------------------------------------------------------------
template <bool FUSE_LIN>
__global__ void __launch_bounds__(256)
conv_ln_kernel(const float* __restrict__ in,     // [B, L, 256]
               const float* __restrict__ w,      // [3, 256, 256]
               const float* __restrict__ bias,   // [256]
               const float* __restrict__ lng,    // [256]
               const float* __restrict__ lnb,    // [256]
               const float* __restrict__ lw,     // [256] (linear weight col)
               const float* __restrict__ lb,     // [1]
               float* __restrict__ out)          // h1 [B,L,256] or dur_pred [B,L]
{
    __shared__ float xs[(TL + 2) * DD];   // 18 KB input halo tile
    __shared__ float wsum[8], wsq[8];
    __shared__ float bro[2];

    const int f  = threadIdx.x;
    const int b  = blockIdx.y;
    const int l0 = blockIdx.x * TL;
    const int lane = f & 31;
    const int wrp  = f >> 5;

    // Load (TL+2) input rows with zero padding at sequence edges
    #pragma unroll
    for (int i = 0; i < TL + 2; i++) {
        int l = l0 - 1 + i;
        xs[i * DD + f] = (l >= 0 && l < LL) ? in[((size_t)b * LL + l) * DD + f] : 0.f;
    }
    __syncthreads();

    float acc[TL];
    float bi = bias[f];
    #pragma unroll
    for (int l = 0; l < TL; l++) acc[l] = bi;

    // Main loop: for each input channel d, reuse weights across TL positions
    for (int d = 0; d < DD; d++) {
        float xr[TL + 2];
        #pragma unroll
        for (int i = 0; i < TL + 2; i++) xr[i] = xs[i * DD + d];  // smem broadcast
        #pragma unroll
        for (int k = 0; k < 3; k++) {
            float wv = w[((size_t)k * DD + d) * FF + f];          // coalesced
            #pragma unroll
            for (int l = 0; l < TL; l++) acc[l] = fmaf(xr[l + k], wv, acc[l]);
        }
    }

    const float gf = lng[f];
    const float bf = lnb[f];
    const float lwf = FUSE_LIN ? lw[f] : 0.f;
    const float lbv = FUSE_LIN ? lb[0] : 0.f;

    // Epilogue: per-position LayerNorm (+ ReLU) and optional linear head
    for (int l = 0; l < TL; l++) {
        float v = acc[l];
        float s = v, q = v * v;
        #pragma unroll
        for (int o = 16; o; o >>= 1) {
            s += __shfl_xor_sync(0xFFFFFFFFu, s, o);
            q += __shfl_xor_sync(0xFFFFFFFFu, q, o);
        }
        if (lane == 0) { wsum[wrp] = s; wsq[wrp] = q; }
        __syncthreads();
        if (f == 0) {
            float S = 0.f, Q = 0.f;
            #pragma unroll
            for (int j = 0; j < 8; j++) { S += wsum[j]; Q += wsq[j]; }
            float mu  = S * (1.f / FF);
            float var = Q * (1.f / FF) - mu * mu;
            bro[0] = mu;
            bro[1] = rsqrtf(var + 1e-5f);
        }
        __syncthreads();
        float h = fmaxf((v - bro[0]) * bro[1] * gf + bf, 0.f);

        if (!FUSE_LIN) {
            out[((size_t)b * LL + l0 + l) * FF + f] = h;
            __syncthreads();  // protect wsum/bro reuse next iter
        } else {
            // linear head: dot(h, lw) + lb, ReLU
            float p = h * lwf;
            #pragma unroll
            for (int o = 16; o; o >>= 1)
                p += __shfl_xor_sync(0xFFFFFFFFu, p, o);
            __syncthreads();  // wsum free for reuse
            if (lane == 0) wsum[wrp] = p;
            __syncthreads();
            if (f == 0) {
                float S = 0.f;
                #pragma unroll
                for (int j = 0; j < 8; j++) S += wsum[j];
                out[(size_t)b * LL + l0 + l] = fmaxf(S + lbv, 0.f);
            }
            __syncthreads();
        }
    }
}

// ---------------------------------------------------------------------------
extern "C" void kernel_launch(void* const* d_in, const int* in_sizes, int n_in,
                              void* d_out, int out_size) {
    const float* x    = (const float*)d_in[0];
    const int*   dur  = (const int*)  d_in[1];
    // d_in[2] = mel_max_length (device scalar) — derive M from out_size instead
    const float* c1w  = (const float*)d_in[3];
    const float* c1b  = (const float*)d_in[4];
    const float* ln1g = (const float*)d_in[5];
    const float* ln1b = (const float*)d_in[6];
    const float* c2w  = (const float*)d_in[7];
    const float* c2b  = (const float*)d_in[8];
    const float* ln2g = (const float*)d_in[9];
    const float* ln2b = (const float*)d_in[10];
    const float* lw   = (const float*)d_in[11];
    const float* lb   = (const float*)d_in[12];

    float* out = (float*)d_out;
    int M = (out_size - BB * LL) / (BB * DD);        // = 4096
    float* dur_pred = out + (size_t)BB * M * DD;

    float* h1;
    cudaGetSymbolAddress((void**)&h1, g_h1);

    // Expand path
    cumsum_kernel<<<BB, LL>>>(dur);
    expand_kernel<<<dim3((M + 7) / 8, BB), 256>>>(x, out, M);

    // Duration predictor path
    conv_ln_kernel<false><<<dim3(LL / TL, BB), 256>>>(
        x, c1w, c1b, ln1g, ln1b, nullptr, nullptr, h1);
    conv_ln_kernel<true><<<dim3(LL / TL, BB), 256>>>(
        h1, c2w, c2b, ln2g, ln2b, lw, lb, dur_pred);
}